// round 13
// baseline (speedup 1.0000x reference)
#include <cuda_runtime.h>
#include <cuda_fp16.h>
#include <math.h>
#include <stdint.h>

// ---- problem constants ----
#define TOK  4096
#define HID  4096
#define NHD  32
#define HDD  128
#define NB   8
#define QL   512
#define HIS  512
#define BSZ  64
#define NBL  16

// ---- scratch ----
__device__ float2 g_cs[TOK * 64];           // per (token, freq) cos/sin
__device__ __half g_Ah[TOK * HID];          // GEMM A operand (hidden, later attn out)
__device__ __half g_Wt[4][HID * HID];       // transposed weights [N,K] fp16
__device__ __half g_Qhi[TOK * HID];
__device__ __half g_Qlo[TOK * HID];
__device__ __half g_Khi[NB * NHD * 1024 * HDD];
__device__ __half g_Klo[NB * NHD * 1024 * HDD];
__device__ __half g_Vh [NB * NHD * 1024 * HDD];

// ============================================================
// helpers
// ============================================================
__device__ __forceinline__ uint32_t smem_u32(const void* p) {
    uint32_t a;
    asm("{ .reg .u64 t; cvta.to.shared.u64 t, %1; cvt.u32.u64 %0, t; }" : "=r"(a) : "l"(p));
    return a;
}
__device__ __forceinline__ void cp16(uint32_t dst, const void* src) {
    asm volatile("cp.async.cg.shared.global [%0], [%1], 16;" :: "r"(dst), "l"(src));
}
__device__ __forceinline__ void cp_commit() {
    asm volatile("cp.async.commit_group;" ::: "memory");
}
template <int N> __device__ __forceinline__ void cp_wait() {
    asm volatile("cp.async.wait_group %0;" :: "n"(N) : "memory");
}
__device__ __forceinline__ void ldm4(uint32_t* r, uint32_t addr) {
    asm volatile("ldmatrix.sync.aligned.m8n8.x4.shared.b16 {%0,%1,%2,%3}, [%4];"
                 : "=r"(r[0]), "=r"(r[1]), "=r"(r[2]), "=r"(r[3]) : "r"(addr));
}
__device__ __forceinline__ void ldm4t(uint32_t* r, uint32_t addr) {
    asm volatile("ldmatrix.sync.aligned.m8n8.x4.trans.shared.b16 {%0,%1,%2,%3}, [%4];"
                 : "=r"(r[0]), "=r"(r[1]), "=r"(r[2]), "=r"(r[3]) : "r"(addr));
}
__device__ __forceinline__ void mmah(float* d, const uint32_t* a, const uint32_t* b) {
    asm volatile(
        "mma.sync.aligned.m16n8k16.row.col.f32.f16.f16.f32 "
        "{%0,%1,%2,%3}, {%4,%5,%6,%7}, {%8,%9}, {%0,%1,%2,%3};"
        : "+f"(d[0]), "+f"(d[1]), "+f"(d[2]), "+f"(d[3])
        : "r"(a[0]), "r"(a[1]), "r"(a[2]), "r"(a[3]), "r"(b[0]), "r"(b[1]));
}
__device__ __forceinline__ uint32_t packh2(float x, float y) {
    __half2 h = __floats2half2_rn(x, y);
    return *reinterpret_cast<uint32_t*>(&h);
}
__device__ __forceinline__ float fexp(float x) {
    float t = fmaxf(x * 1.4426950408889634f, -80.0f);
    int   i = __float2int_rn(t);
    float f = t - (float)i;
    float p = 0.0013333558f;
    p = fmaf(p, f, 0.0096181291f);
    p = fmaf(p, f, 0.0555041087f);
    p = fmaf(p, f, 0.2402265069f);
    p = fmaf(p, f, 0.6931471806f);
    p = fmaf(p, f, 1.0f);
    return p * __int_as_float((i + 127) << 23);
}

// ============================================================
// fp32 -> fp16 convert
// ============================================================
__global__ __launch_bounds__(256) void cvt_half(const float4* __restrict__ src,
                                                __half* __restrict__ dst)
{
    int i = blockIdx.x * 256 + threadIdx.x;
    float4 v = src[i];
    __half2* d = (__half2*)dst;
    d[i * 2]     = __floats2half2_rn(v.x, v.y);
    d[i * 2 + 1] = __floats2half2_rn(v.z, v.w);
}

// ============================================================
// RoPE angle table: one thread per (t, j<64).
// ============================================================
__global__ __launch_bounds__(256) void rope_tab(const int* __restrict__ pos,
                                                float2* __restrict__ cs)
{
    const int idx = blockIdx.x * 256 + threadIdx.x;   // t*64 + j
    const int j = idx & 63, t = idx >> 6;
    const double inv_freq = exp2(-(double)j * (13.287712379549449 / 64.0));
    const double ang = (double)pos[t] * inv_freq;
    const float a = (float)remainder(ang, 6.283185307179586476925286766559);
    cs[idx] = make_float2(cosf(a), sinf(a));
}

// ============================================================
// Transpose 4 weights W[K,N] fp32 -> Wt[N,K] fp16 (z = which)
// ============================================================
__global__ __launch_bounds__(256) void transpose_half4(
    const float* __restrict__ W0, const float* __restrict__ W1,
    const float* __restrict__ W2, const float* __restrict__ W3,
    __half* __restrict__ dst)
{
    __shared__ float tile[32][33];
    const int bx = blockIdx.x, by = blockIdx.y, bz = blockIdx.z;
    const float* W = (bz == 0) ? W0 : (bz == 1) ? W1 : (bz == 2) ? W2 : W3;
    __half* out = dst + (size_t)bz * HID * HID;
    const int tx = threadIdx.x & 31, ty = threadIdx.x >> 5;
#pragma unroll
    for (int j = 0; j < 4; j++)
        tile[ty + j * 8][tx] = W[(size_t)(by * 32 + ty + j * 8) * HID + bx * 32 + tx];
    __syncthreads();
#pragma unroll
    for (int j = 0; j < 4; j++) {
        float v = tile[tx][ty + j * 8];
        out[(size_t)(bx * 32 + ty + j * 8) * HID + by * 32 + tx] = __float2half(v);
    }
}

// ============================================================
// History KV prep: paged cache -> [b][h][p<512][d] fp16 bufs.
// ============================================================
__global__ __launch_bounds__(256) void hist_prep(
    const float* __restrict__ kcache, const float* __restrict__ vcache,
    const int* __restrict__ boff,
    __half* __restrict__ Khi, __half* __restrict__ Klo, __half* __restrict__ Vh)
{
    const int idx = blockIdx.x * 8 + (threadIdx.x >> 5);
    const int lane = threadIdx.x & 31;
    const int p = idx & 511;
    const int h = (idx >> 9) & 31;
    const int b = idx >> 14;

    int blk = boff[b * NBL + (p >> 6)];
    size_t base = (((size_t)blk * BSZ + (p & 63)) * NHD + h) * HDD + lane * 4;
    float4 kv = *(const float4*)(kcache + base);
    float4 vv = *(const float4*)(vcache + base);

    const size_t o = ((((size_t)(b * NHD + h)) << 10) + p) * HDD + lane * 4;
    __half khx = __float2half(kv.x), khy = __float2half(kv.y);
    __half khz = __float2half(kv.z), khw = __float2half(kv.w);
    *(__half2*)(Khi + o)     = __half2(khx, khy);
    *(__half2*)(Khi + o + 2) = __half2(khz, khw);
    *(__half2*)(Klo + o)     = __half2(__float2half(kv.x - __half2float(khx)),
                                       __float2half(kv.y - __half2float(khy)));
    *(__half2*)(Klo + o + 2) = __half2(__float2half(kv.z - __half2float(khz)),
                                       __float2half(kv.w - __half2float(khw)));
    *(__half2*)(Vh + o)      = __floats2half2_rn(vv.x, vv.y);
    *(__half2*)(Vh + o + 2)  = __floats2half2_rn(vv.z, vv.w);
}

// ============================================================
// fp16 HMMA GEMM core: CTA 128x128, BK=64, 3-stage cp.async,
// 4 warps, warp tile 64x64, fp32 accumulate. Single sync per
// 64-k block (128 MMAs/warp between barriers).
// MODE 0: write fp32 C.   MODE 1: fused rope/scale/split epilogue.
// ============================================================
#define ROWB   144                   // 64 halfs (128B) + 16B pad -> (9r+c)%8 conflict-free
#define TILEB  (128 * ROWB)          // 18432 B
#define STAGEB (2 * TILEB)           // 36864 B
#define NSTG   3
#define GEMM_SMEM (NSTG * STAGEB)    // 110592 B (>= 128*132*4 epilogue tile)
#define EPS 132                      // epilogue smem row stride (floats)

template <int MODE>
__device__ __forceinline__ void gemm_core(const __half* __restrict__ A,
                                          const __half* __restrict__ B,
                                          float* __restrict__ C,
                                          const float2* __restrict__ cs,
                                          __half* __restrict__ Qhi, __half* __restrict__ Qlo,
                                          __half* __restrict__ Khi, __half* __restrict__ Klo,
                                          __half* __restrict__ Vh,
                                          int row0, int col0, int widx)
{
    extern __shared__ char smem[];
    const uint32_t sbase = smem_u32(smem);
    const int tid = threadIdx.x;
    const int lane = tid & 31, wid = tid >> 5;
    const int wm = wid & 1, wn = wid >> 1;

    const __half* tsrc[2] = { A + (size_t)row0 * HID, B + (size_t)col0 * HID };

    // 2 tiles * 128 rows * 4 chunks16B... now 8 chunks per row (64 halfs)
    auto fill = [&](int stage, int kblk) {
        const uint32_t sb = sbase + stage * STAGEB;
        const int koff = kblk * 64;
#pragma unroll
        for (int i = 0; i < 16; i++) {
            int id = tid + i * 128;
            int t = id >> 10;
            int r = (id >> 3) & 127;
            int c = id & 7;
            cp16(sb + t * TILEB + r * ROWB + c * 16,
                 tsrc[t] + (size_t)r * HID + koff + c * 8);
        }
        cp_commit();
    };

    float acc[4][8][4];
#pragma unroll
    for (int i = 0; i < 4; i++)
#pragma unroll
        for (int j = 0; j < 8; j++)
#pragma unroll
            for (int u = 0; u < 4; u++) acc[i][j][u] = 0.f;

    fill(0, 0); fill(1, 1);

    const int a_row = (lane & 15);
    const int a_cb  = (lane >> 4) * 16;
    const int b_row = (lane & 7) + ((lane >> 4) << 3);
    const int b_cb  = ((lane >> 3) & 1) * 16;

    const int NKB = HID / 64;   // 64 k-blocks
    for (int c = 0; c < NKB; ++c) {
        cp_wait<1>();
        __syncthreads();
        if (c + 2 < NKB) fill((c + 2) % 3, c + 2);

        const int s = c % 3;
        const uint32_t sb = sbase + s * STAGEB;
        const uint32_t aA = sb + (wm * 64 + a_row) * ROWB + a_cb;
        const uint32_t aB = sb + TILEB + (wn * 64 + b_row) * ROWB + b_cb;

#pragma unroll
        for (int ks = 0; ks < 4; ++ks) {
            const int kb = ks * 32;          // 16 halfs = 32 bytes per k-chunk
            uint32_t a[4][4], b[4][4];
#pragma unroll
            for (int i = 0; i < 4; i++) ldm4(a[i], aA + i * (16 * ROWB) + kb);
#pragma unroll
            for (int j = 0; j < 4; j++) ldm4(b[j], aB + j * (16 * ROWB) + kb);
#pragma unroll
            for (int i = 0; i < 4; i++)
#pragma unroll
                for (int j = 0; j < 8; j++)
                    mmah(acc[i][j], a[i], &b[j >> 1][(j & 1) * 2]);
        }
    }

    if (MODE == 0) {
        const int erow = row0 + wm * 64 + (lane >> 2);
        const int ecol = col0 + wn * 64 + (lane & 3) * 2;
#pragma unroll
        for (int i = 0; i < 4; i++)
#pragma unroll
            for (int j = 0; j < 8; j++) {
                float* p0 = C + (size_t)(erow + i * 16) * HID + ecol + j * 8;
                float* p1 = C + (size_t)(erow + i * 16 + 8) * HID + ecol + j * 8;
                *(float2*)p0 = make_float2(acc[i][j][0], acc[i][j][1]);
                *(float2*)p1 = make_float2(acc[i][j][2], acc[i][j][3]);
            }
        return;
    }

    // ---- MODE 1: fused epilogue (rope / scale / split / fp16 out) ----
    cp_wait<0>();
    __syncthreads();               // pipeline smem dead; reuse as fp32 tile
    float* S = (float*)smem;
    const int srow = wm * 64 + (lane >> 2);
    const int scol = wn * 64 + (lane & 3) * 2;
#pragma unroll
    for (int i = 0; i < 4; i++)
#pragma unroll
        for (int j = 0; j < 8; j++) {
            *(float2*)&S[(srow + i * 16) * EPS + scol + j * 8]     = make_float2(acc[i][j][0], acc[i][j][1]);
            *(float2*)&S[(srow + i * 16 + 8) * EPS + scol + j * 8] = make_float2(acc[i][j][2], acc[i][j][3]);
        }
    __syncthreads();

    const int head = col0 >> 7;
    const int c0 = lane * 4;
    const float scale = 0.08838834764831845f;

    for (int it = 0; it < 32; ++it) {
        const int r = wid * 32 + it;
        const int t = row0 + r;
        float4 x = *(float4*)&S[r * EPS + c0];

        if (widx == 2) {
            // V: convert only -> [b][h][512+local][d]
            const int b = t >> 9;
            const size_t rowid = (((size_t)(b * NHD + head)) << 10) + HIS + (t & 511);
            uint2 pk = make_uint2(packh2(x.x, x.y), packh2(x.z, x.w));
            *(uint2*)(Vh + rowid * HDD + c0) = pk;
        } else {
            float4 y = *(float4*)&S[r * EPS + (c0 ^ 64)];
            const int j = c0 & 63;
            const float2* ct = cs + t * 64 + j;
            const bool hiHalf = c0 >= 64;
            float xs[4] = { x.x, x.y, x.z, x.w };
            float ys[4] = { y.x, y.y, y.z, y.w };
            float vr[4];
#pragma unroll
            for (int i = 0; i < 4; i++) {
                float2 cv = ct[i];
                vr[i] = hiHalf ? (xs[i] * cv.x + ys[i] * cv.y)
                               : (xs[i] * cv.x - ys[i] * cv.y);
            }
            if (widx == 0) {
#pragma unroll
                for (int i = 0; i < 4; i++) vr[i] *= scale;
            }
            __half hh[4];
            float  lo[4];
#pragma unroll
            for (int i = 0; i < 4; i++) {
                hh[i] = __float2half(vr[i]);
                lo[i] = vr[i] - __half2float(hh[i]);
            }
            __half2 h01 = __half2(hh[0], hh[1]), h23 = __half2(hh[2], hh[3]);
            uint2 phh = make_uint2(*(uint32_t*)&h01, *(uint32_t*)&h23);
            uint2 plo = make_uint2(packh2(lo[0], lo[1]), packh2(lo[2], lo[3]));
            if (widx == 0) {
                const size_t o = (size_t)t * HID + head * HDD + c0;
                *(uint2*)(Qhi + o) = phh;
                *(uint2*)(Qlo + o) = plo;
            } else {
                const int b = t >> 9;
                const size_t rowid = (((size_t)(b * NHD + head)) << 10) + HIS + (t & 511);
                const size_t o = rowid * HDD + c0;
                *(uint2*)(Khi + o) = phh;
                *(uint2*)(Klo + o) = plo;
            }
        }
    }
}

// fused QKV + rope/split epilogue: grid.x = 96, grid.y = 32
__global__ __launch_bounds__(128, 2) void gemm_qkv(const __half* __restrict__ A,
                                                   const __half* __restrict__ Wt,
                                                   const float2* __restrict__ cs,
                                                   __half* __restrict__ Qhi, __half* __restrict__ Qlo,
                                                   __half* __restrict__ Khi, __half* __restrict__ Klo,
                                                   __half* __restrict__ Vh)
{
    const int widx = blockIdx.x >> 5;
    const int col0 = (blockIdx.x & 31) * 128;
    const int row0 = blockIdx.y * 128;
    gemm_core<1>(A, Wt + (size_t)widx * HID * HID, nullptr, cs,
                 Qhi, Qlo, Khi, Klo, Vh, row0, col0, widx);
}

__global__ __launch_bounds__(128, 2) void gemm_single(const __half* __restrict__ A,
                                                      const __half* __restrict__ B,
                                                      float* __restrict__ C)
{
    gemm_core<0>(A, B, C, nullptr, nullptr, nullptr, nullptr, nullptr, nullptr,
                 blockIdx.y * 128, blockIdx.x * 128, 0);
}

// ============================================================
// HMMA flash attention. Grid (qt=4, h=32, b=8), 256 threads.
// Q tile 128x128 (pre-split fp16 via cp.async), KV tile 64,
// 3-stage cp.async pipeline, single sync per tile. Output fp16.
// ============================================================
#define AS 136
#define QLO_OFF (128 * AS)
#define KV_BASE (2 * 128 * AS)
#define KV_STG  (3 * 64 * AS)
#define ATT_SMEM ((KV_BASE + 3 * KV_STG) * 2)   // 226304 bytes

__global__ __launch_bounds__(256, 1) void attn_mma(
    const __half* __restrict__ Qhi, const __half* __restrict__ Qlo,
    const __half* __restrict__ Khi, const __half* __restrict__ Klo,
    const __half* __restrict__ Vh, __half* __restrict__ obuf)
{
    extern __shared__ __half hsm[];
    const int qt = blockIdx.x, h = blockIdx.y, b = blockIdx.z;
    const int tid = threadIdx.x;
    const int lane = tid & 31, w = tid >> 5;

    const size_t kvoff = ((size_t)(b * NHD + h)) * 1024 * HDD;
    const __half* kp[3] = { Khi + kvoff, Klo + kvoff, Vh + kvoff };
    const uint32_t sb = smem_u32(hsm);

    // Q tiles via cp.async (part of group 0)
    {
        const __half* qh_src = Qhi + (size_t)(b * QL + qt * 128) * HID + h * HDD;
        const __half* ql_src = Qlo + (size_t)(b * QL + qt * 128) * HID + h * HDD;
#pragma unroll
        for (int i = 0; i < 8; i++) {
            int id = tid + i * 256;
            int r = id >> 4;
            int c = id & 15;
            cp16(sb + (uint32_t)(r * AS + c * 8) * 2,           qh_src + (size_t)r * HID + c * 8);
            cp16(sb + (uint32_t)(QLO_OFF + r * AS + c * 8) * 2, ql_src + (size_t)r * HID + c * 8);
        }
    }

    auto fill = [&](int stage, int kt) {
#pragma unroll
        for (int i = 0; i < 12; i++) {
            int id = tid + i * 256;
            int buf = id >> 10;
            int r = (id >> 4) & 63;
            int c = id & 15;
            uint32_t dst = sb + (uint32_t)(KV_BASE + stage * KV_STG + buf * (64 * AS) + r * AS + c * 8) * 2;
            cp16(dst, kp[buf] + (size_t)(kt * 64 + r) * HDD + c * 8);
        }
        cp_commit();
    };

    float m0 = -1e30f, m1 = -1e30f, l0 = 0.f, l1 = 0.f;
    float o[16][4];
#pragma unroll
    for (int d = 0; d < 16; d++)
#pragma unroll
        for (int u = 0; u < 4; u++) o[d][u] = 0.f;

    const int r0 = lane >> 2;
    const int qp0 = HIS + qt * 128 + w * 16 + r0;
    const int qp1 = qp0 + 8;

    const uint32_t aQh = sb + ((w * 16 + (lane & 15)) * AS + (lane >> 4) * 8) * 2;
    const uint32_t aQl = aQh + QLO_OFF * 2;
    const uint32_t aKrow = (lane & 7) + ((lane >> 4) << 3);
    const uint32_t aKcb  = ((lane >> 3) & 1) * 8;
    const uint32_t aVrow = (lane & 7) + ((lane >> 3) & 1) * 8;
    const uint32_t aVcb  = (lane >> 4) * 8;

    const int ntiles = 10 + 2 * qt;
    fill(0, 0);
    fill(1, 1);

    for (int kt = 0; kt < ntiles; kt++) {
        const int s = kt % 3;
        cp_wait<1>();
        __syncthreads();
        if (kt + 2 < ntiles) fill((kt + 2) % 3, kt + 2);

        const uint32_t kbs = sb + (uint32_t)(KV_BASE + s * KV_STG) * 2;
        const uint32_t vbs = kbs + (uint32_t)(2 * 64 * AS) * 2;

        float S[8][4];
#pragma unroll
        for (int f = 0; f < 8; f++)
#pragma unroll
            for (int u = 0; u < 4; u++) S[f][u] = 0.f;

#pragma unroll
        for (int kc = 0; kc < 8; kc++) {
            uint32_t qh[4], ql[4];
            ldm4(qh, aQh + kc * 32);
            ldm4(ql, aQl + kc * 32);
#pragma unroll
            for (int jp = 0; jp < 4; jp++) {
                uint32_t kh[4], kl[4];
                const uint32_t ka = kbs + ((jp * 16 + aKrow) * AS + aKcb + kc * 16) * 2;
                ldm4(kh, ka);
                ldm4(kl, ka + (uint32_t)(64 * AS) * 2);
                mmah(S[2*jp],   qh, &kh[0]);
                mmah(S[2*jp],   qh, &kl[0]);
                mmah(S[2*jp],   ql, &kh[0]);
                mmah(S[2*jp+1], qh, &kh[2]);
                mmah(S[2*jp+1], qh, &kl[2]);
                mmah(S[2*jp+1], ql, &kh[2]);
            }
        }

        if (kt >= ntiles - 2) {
#pragma unroll
            for (int f = 0; f < 8; f++) {
                int c0 = kt * 64 + f * 8 + (lane & 3) * 2;
                if (c0     > qp0) S[f][0] = -1e30f;
                if (c0 + 1 > qp0) S[f][1] = -1e30f;
                if (c0     > qp1) S[f][2] = -1e30f;
                if (c0 + 1 > qp1) S[f][3] = -1e30f;
            }
        }

        float tm0 = -1e30f, tm1 = -1e30f;
#pragma unroll
        for (int f = 0; f < 8; f++) {
            tm0 = fmaxf(tm0, fmaxf(S[f][0], S[f][1]));
            tm1 = fmaxf(tm1, fmaxf(S[f][2], S[f][3]));
        }
        tm0 = fmaxf(tm0, __shfl_xor_sync(0xffffffffu, tm0, 1));
        tm0 = fmaxf(tm0, __shfl_xor_sync(0xffffffffu, tm0, 2));
        tm1 = fmaxf(tm1, __shfl_xor_sync(0xffffffffu, tm1, 1));
        tm1 = fmaxf(tm1, __shfl_xor_sync(0xffffffffu, tm1, 2));
        const float mn0 = fmaxf(m0, tm0), mn1 = fmaxf(m1, tm1);
        const float al0 = fexp(m0 - mn0), al1 = fexp(m1 - mn1);

        float s0 = 0.f, s1 = 0.f;
#pragma unroll
        for (int f = 0; f < 8; f++) {
            S[f][0] = fexp(S[f][0] - mn0);
            S[f][1] = fexp(S[f][1] - mn0);
            S[f][2] = fexp(S[f][2] - mn1);
            S[f][3] = fexp(S[f][3] - mn1);
            s0 += S[f][0] + S[f][1];
            s1 += S[f][2] + S[f][3];
        }
        s0 += __shfl_xor_sync(0xffffffffu, s0, 1);
        s0 += __shfl_xor_sync(0xffffffffu, s0, 2);
        s1 += __shfl_xor_sync(0xffffffffu, s1, 1);
        s1 += __shfl_xor_sync(0xffffffffu, s1, 2);
        l0 = l0 * al0 + s0;
        l1 = l1 * al1 + s1;
        m0 = mn0; m1 = mn1;

#pragma unroll
        for (int d = 0; d < 16; d++) {
            o[d][0] *= al0; o[d][1] *= al0;
            o[d][2] *= al1; o[d][3] *= al1;
        }

        uint32_t pa[4][4];
#pragma unroll
        for (int kk = 0; kk < 4; kk++) {
            pa[kk][0] = packh2(S[2*kk][0],   S[2*kk][1]);
            pa[kk][1] = packh2(S[2*kk][2],   S[2*kk][3]);
            pa[kk][2] = packh2(S[2*kk+1][0], S[2*kk+1][1]);
            pa[kk][3] = packh2(S[2*kk+1][2], S[2*kk+1][3]);
        }

#pragma unroll
        for (int kk = 0; kk < 4; kk++) {
#pragma unroll
            for (int dg = 0; dg < 8; dg++) {
                uint32_t bv[4];
                ldm4t(bv, vbs + ((kk * 16 + aVrow) * AS + dg * 16 + aVcb) * 2);
                mmah(o[dg*2],   pa[kk], &bv[0]);
                mmah(o[dg*2+1], pa[kk], &bv[2]);
            }
        }
    }

    const float inv0 = 1.f / l0, inv1 = 1.f / l1;
    const int gr0 = b * QL + qt * 128 + w * 16 + r0;
    const int gr1 = gr0 + 8;
    const int col = h * HDD + (lane & 3) * 2;
#pragma unroll
    for (int d = 0; d < 16; d++) {
        *(__half2*)(obuf + (size_t)gr0 * HID + col + d * 8) = __floats2half2_rn(o[d][0] * inv0, o[d][1] * inv0);
        *(__half2*)(obuf + (size_t)gr1 * HID + col + d * 8) = __floats2half2_rn(o[d][2] * inv1, o[d][3] * inv1);
    }
}

// ============================================================
// launch — fork/join streams so independent prep kernels overlap
// ============================================================
extern "C" void kernel_launch(void* const* d_in, const int* in_sizes, int n_in,
                              void* d_out, int out_size)
{
    const float* hidden = (const float*)d_in[0];
    const float* Wq     = (const float*)d_in[1];
    const float* Wk     = (const float*)d_in[2];
    const float* Wv     = (const float*)d_in[3];
    const float* Wo     = (const float*)d_in[4];
    const float* kcache = (const float*)d_in[5];
    const float* vcache = (const float*)d_in[6];
    const int*   boff   = (const int*)d_in[7];
    const int*   pos    = (const int*)d_in[8];
    float* out = (float*)d_out;

    float2* cs;
    __half *ah, *wt, *qhi, *qlo, *khi, *klo, *vh;
    cudaGetSymbolAddress((void**)&cs, g_cs);
    cudaGetSymbolAddress((void**)&ah, g_Ah);
    cudaGetSymbolAddress((void**)&wt, g_Wt);
    cudaGetSymbolAddress((void**)&qhi, g_Qhi);
    cudaGetSymbolAddress((void**)&qlo, g_Qlo);
    cudaGetSymbolAddress((void**)&khi, g_Khi);
    cudaGetSymbolAddress((void**)&klo, g_Klo);
    cudaGetSymbolAddress((void**)&vh, g_Vh);

    // one-time setup (runs during the uncaptured correctness call first)
    static bool s_init = false;
    static cudaStream_t s_str[3];
    static cudaEvent_t  s_root, s_ev[3];
    if (!s_init) {
        cudaFuncSetAttribute(gemm_qkv, cudaFuncAttributeMaxDynamicSharedMemorySize, GEMM_SMEM);
        cudaFuncSetAttribute(gemm_single, cudaFuncAttributeMaxDynamicSharedMemorySize, GEMM_SMEM);
        cudaFuncSetAttribute(attn_mma, cudaFuncAttributeMaxDynamicSharedMemorySize, ATT_SMEM);
        for (int i = 0; i < 3; i++)
            cudaStreamCreateWithFlags(&s_str[i], cudaStreamNonBlocking);
        cudaEventCreateWithFlags(&s_root, cudaEventDisableTiming);
        for (int i = 0; i < 3; i++)
            cudaEventCreateWithFlags(&s_ev[i], cudaEventDisableTiming);
        s_init = true;
    }

    const int ncvt = TOK * HID / 4 / 256;
    dim3 tgrid(HID / 32, HID / 32, 4);

    // fork
    cudaEventRecord(s_root, 0);
    cudaStreamWaitEvent(s_str[0], s_root, 0);
    cudaStreamWaitEvent(s_str[1], s_root, 0);
    cudaStreamWaitEvent(s_str[2], s_root, 0);

    // side streams: independent prep
    rope_tab<<<TOK * 64 / 256, 256, 0, s_str[0]>>>(pos, cs);
    cudaEventRecord(s_ev[0], s_str[0]);

    transpose_half4<<<tgrid, 256, 0, s_str[1]>>>(Wq, Wk, Wv, Wo, wt);
    cudaEventRecord(s_ev[1], s_str[1]);

    hist_prep<<<NB * NHD * HIS / 8, 256, 0, s_str[2]>>>(kcache, vcache, boff, khi, klo, vh);
    cudaEventRecord(s_ev[2], s_str[2]);

    // main stream: A convert (runs concurrently with side streams)
    cvt_half<<<ncvt, 256>>>((const float4*)hidden, ah);

    // join rope_tab + transpose before QKV GEMM
    cudaStreamWaitEvent(0, s_ev[0], 0);
    cudaStreamWaitEvent(0, s_ev[1], 0);

    dim3 qkvgrid(3 * HID / 128, TOK / 128);
    gemm_qkv<<<qkvgrid, 128, GEMM_SMEM>>>(ah, wt, cs, qhi, qlo, khi, klo, vh);

    // join hist_prep before attention (hidden under the QKV GEMM)
    cudaStreamWaitEvent(0, s_ev[2], 0);

    dim3 ag(QL / 128, NHD, NB);
    attn_mma<<<ag, 256, ATT_SMEM>>>(qhi, qlo, khi, klo, vh, ah);

    dim3 ogrid(HID / 128, TOK / 128);
    gemm_single<<<ogrid, 128, GEMM_SMEM>>>(ah, wt + 3 * (size_t)HID * HID, out);
}

// round 16
// speedup vs baseline: 1.0339x; 1.0339x over previous
#include <cuda_runtime.h>
#include <cuda_fp16.h>
#include <math.h>
#include <stdint.h>

// ---- problem constants ----
#define TOK  4096
#define HID  4096
#define NHD  32
#define HDD  128
#define NB   8
#define QL   512
#define HIS  512
#define BSZ  64
#define NBL  16

// ---- scratch ----
__device__ float2 g_cs[TOK * 64];           // per (token, freq) cos/sin
__device__ __half g_Ah[TOK * HID];          // GEMM A operand (hidden, later attn out)
__device__ __half g_Wt[4][HID * HID];       // transposed weights [N,K] fp16
__device__ __half g_Qh [TOK * HID];
__device__ __half g_Khi[NB * NHD * 1024 * HDD];
__device__ __half g_Klo[NB * NHD * 1024 * HDD];
__device__ __half g_Vh [NB * NHD * 1024 * HDD];

// ============================================================
// helpers
// ============================================================
__device__ __forceinline__ uint32_t smem_u32(const void* p) {
    uint32_t a;
    asm("{ .reg .u64 t; cvta.to.shared.u64 t, %1; cvt.u32.u64 %0, t; }" : "=r"(a) : "l"(p));
    return a;
}
__device__ __forceinline__ void cp16(uint32_t dst, const void* src) {
    asm volatile("cp.async.cg.shared.global [%0], [%1], 16;" :: "r"(dst), "l"(src));
}
__device__ __forceinline__ void cp_commit() {
    asm volatile("cp.async.commit_group;" ::: "memory");
}
template <int N> __device__ __forceinline__ void cp_wait() {
    asm volatile("cp.async.wait_group %0;" :: "n"(N) : "memory");
}
__device__ __forceinline__ void ldm4(uint32_t* r, uint32_t addr) {
    asm volatile("ldmatrix.sync.aligned.m8n8.x4.shared.b16 {%0,%1,%2,%3}, [%4];"
                 : "=r"(r[0]), "=r"(r[1]), "=r"(r[2]), "=r"(r[3]) : "r"(addr));
}
__device__ __forceinline__ void ldm4t(uint32_t* r, uint32_t addr) {
    asm volatile("ldmatrix.sync.aligned.m8n8.x4.trans.shared.b16 {%0,%1,%2,%3}, [%4];"
                 : "=r"(r[0]), "=r"(r[1]), "=r"(r[2]), "=r"(r[3]) : "r"(addr));
}
__device__ __forceinline__ void mmah(float* d, const uint32_t* a, const uint32_t* b) {
    asm volatile(
        "mma.sync.aligned.m16n8k16.row.col.f32.f16.f16.f32 "
        "{%0,%1,%2,%3}, {%4,%5,%6,%7}, {%8,%9}, {%0,%1,%2,%3};"
        : "+f"(d[0]), "+f"(d[1]), "+f"(d[2]), "+f"(d[3])
        : "r"(a[0]), "r"(a[1]), "r"(a[2]), "r"(a[3]), "r"(b[0]), "r"(b[1]));
}
__device__ __forceinline__ uint32_t packh2(float x, float y) {
    __half2 h = __floats2half2_rn(x, y);
    return *reinterpret_cast<uint32_t*>(&h);
}
__device__ __forceinline__ float fexp(float x) {
    float t = fmaxf(x * 1.4426950408889634f, -80.0f);
    int   i = __float2int_rn(t);
    float f = t - (float)i;
    float p = 0.0013333558f;
    p = fmaf(p, f, 0.0096181291f);
    p = fmaf(p, f, 0.0555041087f);
    p = fmaf(p, f, 0.2402265069f);
    p = fmaf(p, f, 0.6931471806f);
    p = fmaf(p, f, 1.0f);
    return p * __int_as_float((i + 127) << 23);
}

// ============================================================
// fp32 -> fp16 convert
// ============================================================
__global__ __launch_bounds__(256) void cvt_half(const float4* __restrict__ src,
                                                __half* __restrict__ dst)
{
    int i = blockIdx.x * 256 + threadIdx.x;
    float4 v = src[i];
    __half2* d = (__half2*)dst;
    d[i * 2]     = __floats2half2_rn(v.x, v.y);
    d[i * 2 + 1] = __floats2half2_rn(v.z, v.w);
}

// ============================================================
// RoPE angle table: one thread per (t, j<64).
// ============================================================
__global__ __launch_bounds__(256) void rope_tab(const int* __restrict__ pos,
                                                float2* __restrict__ cs)
{
    const int idx = blockIdx.x * 256 + threadIdx.x;   // t*64 + j
    const int j = idx & 63, t = idx >> 6;
    const double inv_freq = exp2(-(double)j * (13.287712379549449 / 64.0));
    const double ang = (double)pos[t] * inv_freq;
    const float a = (float)remainder(ang, 6.283185307179586476925286766559);
    cs[idx] = make_float2(cosf(a), sinf(a));
}

// ============================================================
// Transpose 4 weights W[K,N] fp32 -> Wt[N,K] fp16 (z = which)
// ============================================================
__global__ __launch_bounds__(256) void transpose_half4(
    const float* __restrict__ W0, const float* __restrict__ W1,
    const float* __restrict__ W2, const float* __restrict__ W3,
    __half* __restrict__ dst)
{
    __shared__ float tile[32][33];
    const int bx = blockIdx.x, by = blockIdx.y, bz = blockIdx.z;
    const float* W = (bz == 0) ? W0 : (bz == 1) ? W1 : (bz == 2) ? W2 : W3;
    __half* out = dst + (size_t)bz * HID * HID;
    const int tx = threadIdx.x & 31, ty = threadIdx.x >> 5;
#pragma unroll
    for (int j = 0; j < 4; j++)
        tile[ty + j * 8][tx] = W[(size_t)(by * 32 + ty + j * 8) * HID + bx * 32 + tx];
    __syncthreads();
#pragma unroll
    for (int j = 0; j < 4; j++) {
        float v = tile[tx][ty + j * 8];
        out[(size_t)(bx * 32 + ty + j * 8) * HID + by * 32 + tx] = __float2half(v);
    }
}

// ============================================================
// History KV prep: paged cache -> [b][h][p<512][d] fp16 bufs.
// ============================================================
__global__ __launch_bounds__(256) void hist_prep(
    const float* __restrict__ kcache, const float* __restrict__ vcache,
    const int* __restrict__ boff,
    __half* __restrict__ Khi, __half* __restrict__ Klo, __half* __restrict__ Vh)
{
    const int idx = blockIdx.x * 8 + (threadIdx.x >> 5);
    const int lane = threadIdx.x & 31;
    const int p = idx & 511;
    const int h = (idx >> 9) & 31;
    const int b = idx >> 14;

    int blk = boff[b * NBL + (p >> 6)];
    size_t base = (((size_t)blk * BSZ + (p & 63)) * NHD + h) * HDD + lane * 4;
    float4 kv = *(const float4*)(kcache + base);
    float4 vv = *(const float4*)(vcache + base);

    const size_t o = ((((size_t)(b * NHD + h)) << 10) + p) * HDD + lane * 4;
    __half khx = __float2half(kv.x), khy = __float2half(kv.y);
    __half khz = __float2half(kv.z), khw = __float2half(kv.w);
    *(__half2*)(Khi + o)     = __half2(khx, khy);
    *(__half2*)(Khi + o + 2) = __half2(khz, khw);
    *(__half2*)(Klo + o)     = __half2(__float2half(kv.x - __half2float(khx)),
                                       __float2half(kv.y - __half2float(khy)));
    *(__half2*)(Klo + o + 2) = __half2(__float2half(kv.z - __half2float(khz)),
                                       __float2half(kv.w - __half2float(khw)));
    *(__half2*)(Vh + o)      = __floats2half2_rn(vv.x, vv.y);
    *(__half2*)(Vh + o + 2)  = __floats2half2_rn(vv.z, vv.w);
}

// ============================================================
// fp16 HMMA GEMM core: CTA 128x128, BK=64, 3-stage cp.async,
// 4 warps, warp tile 64x64, fp32 accumulate. Single-sync loop.
// MODE 0: write fp32 C.   MODE 1: fused rope/scale/split epilogue.
// ============================================================
#define ROWB   144                   // 64 halfs + 16B pad -> conflict-free ldmatrix
#define TILEB  (128 * ROWB)
#define STAGEB (2 * TILEB)
#define NSTG   3
#define GEMM_SMEM (NSTG * STAGEB)    // 110592 B (>= 128*132*4 epilogue tile)
#define EPS 132                      // epilogue smem row stride (floats)

template <int MODE>
__device__ __forceinline__ void gemm_core(const __half* __restrict__ A,
                                          const __half* __restrict__ B,
                                          float* __restrict__ C,
                                          const float2* __restrict__ cs,
                                          __half* __restrict__ Qh,
                                          __half* __restrict__ Khi, __half* __restrict__ Klo,
                                          __half* __restrict__ Vh,
                                          int row0, int col0, int widx)
{
    extern __shared__ char smem[];
    const uint32_t sbase = smem_u32(smem);
    const int tid = threadIdx.x;
    const int lane = tid & 31, wid = tid >> 5;
    const int wm = wid & 1, wn = wid >> 1;

    const __half* tsrc[2] = { A + (size_t)row0 * HID, B + (size_t)col0 * HID };

    auto fill = [&](int stage, int kblk) {
        const uint32_t sb = sbase + stage * STAGEB;
        const int koff = kblk * 64;
#pragma unroll
        for (int i = 0; i < 16; i++) {
            int id = tid + i * 128;
            int t = id >> 10;
            int r = (id >> 3) & 127;
            int c = id & 7;
            cp16(sb + t * TILEB + r * ROWB + c * 16,
                 tsrc[t] + (size_t)r * HID + koff + c * 8);
        }
        cp_commit();
    };

    float acc[4][8][4];
#pragma unroll
    for (int i = 0; i < 4; i++)
#pragma unroll
        for (int j = 0; j < 8; j++)
#pragma unroll
            for (int u = 0; u < 4; u++) acc[i][j][u] = 0.f;

    fill(0, 0); fill(1, 1);

    const int a_row = (lane & 15);
    const int a_cb  = (lane >> 4) * 16;
    const int b_row = (lane & 7) + ((lane >> 4) << 3);
    const int b_cb  = ((lane >> 3) & 1) * 16;

    const int NKB = HID / 64;
    for (int c = 0; c < NKB; ++c) {
        cp_wait<1>();
        __syncthreads();
        if (c + 2 < NKB) fill((c + 2) % 3, c + 2);

        const int s = c % 3;
        const uint32_t sb = sbase + s * STAGEB;
        const uint32_t aA = sb + (wm * 64 + a_row) * ROWB + a_cb;
        const uint32_t aB = sb + TILEB + (wn * 64 + b_row) * ROWB + b_cb;

#pragma unroll
        for (int ks = 0; ks < 4; ++ks) {
            const int kb = ks * 32;
            uint32_t a[4][4], b[4][4];
#pragma unroll
            for (int i = 0; i < 4; i++) ldm4(a[i], aA + i * (16 * ROWB) + kb);
#pragma unroll
            for (int j = 0; j < 4; j++) ldm4(b[j], aB + j * (16 * ROWB) + kb);
#pragma unroll
            for (int i = 0; i < 4; i++)
#pragma unroll
                for (int j = 0; j < 8; j++)
                    mmah(acc[i][j], a[i], &b[j >> 1][(j & 1) * 2]);
        }
    }

    if (MODE == 0) {
        const int erow = row0 + wm * 64 + (lane >> 2);
        const int ecol = col0 + wn * 64 + (lane & 3) * 2;
#pragma unroll
        for (int i = 0; i < 4; i++)
#pragma unroll
            for (int j = 0; j < 8; j++) {
                float* p0 = C + (size_t)(erow + i * 16) * HID + ecol + j * 8;
                float* p1 = C + (size_t)(erow + i * 16 + 8) * HID + ecol + j * 8;
                *(float2*)p0 = make_float2(acc[i][j][0], acc[i][j][1]);
                *(float2*)p1 = make_float2(acc[i][j][2], acc[i][j][3]);
            }
        return;
    }

    // ---- MODE 1: fused epilogue (rope / scale / split / fp16 out) ----
    cp_wait<0>();
    __syncthreads();               // pipeline smem dead; reuse as fp32 tile
    float* S = (float*)smem;
    const int srow = wm * 64 + (lane >> 2);
    const int scol = wn * 64 + (lane & 3) * 2;
#pragma unroll
    for (int i = 0; i < 4; i++)
#pragma unroll
        for (int j = 0; j < 8; j++) {
            *(float2*)&S[(srow + i * 16) * EPS + scol + j * 8]     = make_float2(acc[i][j][0], acc[i][j][1]);
            *(float2*)&S[(srow + i * 16 + 8) * EPS + scol + j * 8] = make_float2(acc[i][j][2], acc[i][j][3]);
        }
    __syncthreads();

    const int head = col0 >> 7;
    const int c0 = lane * 4;
    const float scale = 0.08838834764831845f;

    for (int it = 0; it < 32; ++it) {
        const int r = wid * 32 + it;
        const int t = row0 + r;
        float4 x = *(float4*)&S[r * EPS + c0];

        if (widx == 2) {
            // V: convert only -> [b][h][512+local][d]
            const int b = t >> 9;
            const size_t rowid = (((size_t)(b * NHD + head)) << 10) + HIS + (t & 511);
            uint2 pk = make_uint2(packh2(x.x, x.y), packh2(x.z, x.w));
            *(uint2*)(Vh + rowid * HDD + c0) = pk;
        } else {
            float4 y = *(float4*)&S[r * EPS + (c0 ^ 64)];
            const int j = c0 & 63;
            const float2* ct = cs + t * 64 + j;
            const bool hiHalf = c0 >= 64;
            float xs[4] = { x.x, x.y, x.z, x.w };
            float ys[4] = { y.x, y.y, y.z, y.w };
            float vr[4];
#pragma unroll
            for (int i = 0; i < 4; i++) {
                float2 cv = ct[i];
                vr[i] = hiHalf ? (xs[i] * cv.x + ys[i] * cv.y)
                               : (xs[i] * cv.x - ys[i] * cv.y);
            }
            if (widx == 0) {
                // Q: scale, single fp16 (no lo term needed)
                uint2 phh;
                phh.x = packh2(vr[0] * scale, vr[1] * scale);
                phh.y = packh2(vr[2] * scale, vr[3] * scale);
                const size_t o = (size_t)t * HID + head * HDD + c0;
                *(uint2*)(Qh + o) = phh;
            } else {
                // K: hi/lo split
                __half hh[4];
                float  lo[4];
#pragma unroll
                for (int i = 0; i < 4; i++) {
                    hh[i] = __float2half(vr[i]);
                    lo[i] = vr[i] - __half2float(hh[i]);
                }
                __half2 h01 = __half2(hh[0], hh[1]), h23 = __half2(hh[2], hh[3]);
                uint2 phh = make_uint2(*(uint32_t*)&h01, *(uint32_t*)&h23);
                uint2 plo = make_uint2(packh2(lo[0], lo[1]), packh2(lo[2], lo[3]));
                const int b = t >> 9;
                const size_t rowid = (((size_t)(b * NHD + head)) << 10) + HIS + (t & 511);
                const size_t o = rowid * HDD + c0;
                *(uint2*)(Khi + o) = phh;
                *(uint2*)(Klo + o) = plo;
            }
        }
    }
}

// fused QKV + rope/split epilogue: grid.x = 96, grid.y = 32
__global__ __launch_bounds__(128, 2) void gemm_qkv(const __half* __restrict__ A,
                                                   const __half* __restrict__ Wt,
                                                   const float2* __restrict__ cs,
                                                   __half* __restrict__ Qh,
                                                   __half* __restrict__ Khi, __half* __restrict__ Klo,
                                                   __half* __restrict__ Vh)
{
    const int widx = blockIdx.x >> 5;
    const int col0 = (blockIdx.x & 31) * 128;
    const int row0 = blockIdx.y * 128;
    gemm_core<1>(A, Wt + (size_t)widx * HID * HID, nullptr, cs,
                 Qh, Khi, Klo, Vh, row0, col0, widx);
}

__global__ __launch_bounds__(128, 2) void gemm_single(const __half* __restrict__ A,
                                                      const __half* __restrict__ B,
                                                      float* __restrict__ C)
{
    gemm_core<0>(A, B, C, nullptr, nullptr, nullptr, nullptr, nullptr,
                 blockIdx.y * 128, blockIdx.x * 128, 0);
}

// ============================================================
// HMMA flash attention. Grid (h=32, b=8, qtz=4), 256 threads.
// qt = 3 - qtz  (longest CTAs launch first: LPT scheduling).
// Q tile 128x128 single fp16, KV tile 64 (K hi/lo + V),
// 3-stage cp.async pipeline. QK = 2 MMAs (qh*kh + qh*kl).
// ============================================================
#define AS 136
#define KV_BASE (128 * AS)            // halfs (Q only)
#define KV_STG  (3 * 64 * AS)
#define ATT_SMEM ((KV_BASE + 3 * KV_STG) * 2)   // 191488 bytes

__global__ __launch_bounds__(256, 1) void attn_mma(
    const __half* __restrict__ Qh,
    const __half* __restrict__ Khi, const __half* __restrict__ Klo,
    const __half* __restrict__ Vh, __half* __restrict__ obuf)
{
    extern __shared__ __half hsm[];
    const int h = blockIdx.x, b = blockIdx.y, qt = 3 - blockIdx.z;
    const int tid = threadIdx.x;
    const int lane = tid & 31, w = tid >> 5;

    const size_t kvoff = ((size_t)(b * NHD + h)) * 1024 * HDD;
    const __half* kp[3] = { Khi + kvoff, Klo + kvoff, Vh + kvoff };
    const uint32_t sb = smem_u32(hsm);

    // Q tile via cp.async (part of group 0)
    {
        const __half* qh_src = Qh + (size_t)(b * QL + qt * 128) * HID + h * HDD;
#pragma unroll
        for (int i = 0; i < 8; i++) {
            int id = tid + i * 256;
            int r = id >> 4;
            int c = id & 15;
            cp16(sb + (uint32_t)(r * AS + c * 8) * 2, qh_src + (size_t)r * HID + c * 8);
        }
    }

    auto fill = [&](int stage, int kt) {
#pragma unroll
        for (int i = 0; i < 12; i++) {
            int id = tid + i * 256;
            int buf = id >> 10;
            int r = (id >> 4) & 63;
            int c = id & 15;
            uint32_t dst = sb + (uint32_t)(KV_BASE + stage * KV_STG + buf * (64 * AS) + r * AS + c * 8) * 2;
            cp16(dst, kp[buf] + (size_t)(kt * 64 + r) * HDD + c * 8);
        }
        cp_commit();
    };

    float m0 = -1e30f, m1 = -1e30f, l0 = 0.f, l1 = 0.f;
    float o[16][4];
#pragma unroll
    for (int d = 0; d < 16; d++)
#pragma unroll
        for (int u = 0; u < 4; u++) o[d][u] = 0.f;

    const int r0 = lane >> 2;
    const int qp0 = HIS + qt * 128 + w * 16 + r0;
    const int qp1 = qp0 + 8;

    const uint32_t aQh = sb + ((w * 16 + (lane & 15)) * AS + (lane >> 4) * 8) * 2;
    const uint32_t aKrow = (lane & 7) + ((lane >> 4) << 3);
    const uint32_t aKcb  = ((lane >> 3) & 1) * 8;
    const uint32_t aVrow = (lane & 7) + ((lane >> 3) & 1) * 8;
    const uint32_t aVcb  = (lane >> 4) * 8;

    const int ntiles = 10 + 2 * qt;
    fill(0, 0);
    fill(1, 1);

    for (int kt = 0; kt < ntiles; kt++) {
        const int s = kt % 3;
        cp_wait<1>();
        __syncthreads();
        if (kt + 2 < ntiles) fill((kt + 2) % 3, kt + 2);

        const uint32_t kbs = sb + (uint32_t)(KV_BASE + s * KV_STG) * 2;
        const uint32_t vbs = kbs + (uint32_t)(2 * 64 * AS) * 2;

        float S[8][4];
#pragma unroll
        for (int f = 0; f < 8; f++)
#pragma unroll
            for (int u = 0; u < 4; u++) S[f][u] = 0.f;

#pragma unroll
        for (int kc = 0; kc < 8; kc++) {
            uint32_t qh[4];
            ldm4(qh, aQh + kc * 32);
#pragma unroll
            for (int jp = 0; jp < 4; jp++) {
                uint32_t kh[4], kl[4];
                const uint32_t ka = kbs + ((jp * 16 + aKrow) * AS + aKcb + kc * 16) * 2;
                ldm4(kh, ka);
                ldm4(kl, ka + (uint32_t)(64 * AS) * 2);
                mmah(S[2*jp],   qh, &kh[0]);
                mmah(S[2*jp],   qh, &kl[0]);
                mmah(S[2*jp+1], qh, &kh[2]);
                mmah(S[2*jp+1], qh, &kl[2]);
            }
        }

        if (kt >= ntiles - 2) {
#pragma unroll
            for (int f = 0; f < 8; f++) {
                int c0 = kt * 64 + f * 8 + (lane & 3) * 2;
                if (c0     > qp0) S[f][0] = -1e30f;
                if (c0 + 1 > qp0) S[f][1] = -1e30f;
                if (c0     > qp1) S[f][2] = -1e30f;
                if (c0 + 1 > qp1) S[f][3] = -1e30f;
            }
        }

        float tm0 = -1e30f, tm1 = -1e30f;
#pragma unroll
        for (int f = 0; f < 8; f++) {
            tm0 = fmaxf(tm0, fmaxf(S[f][0], S[f][1]));
            tm1 = fmaxf(tm1, fmaxf(S[f][2], S[f][3]));
        }
        tm0 = fmaxf(tm0, __shfl_xor_sync(0xffffffffu, tm0, 1));
        tm0 = fmaxf(tm0, __shfl_xor_sync(0xffffffffu, tm0, 2));
        tm1 = fmaxf(tm1, __shfl_xor_sync(0xffffffffu, tm1, 1));
        tm1 = fmaxf(tm1, __shfl_xor_sync(0xffffffffu, tm1, 2));
        const float mn0 = fmaxf(m0, tm0), mn1 = fmaxf(m1, tm1);
        const float al0 = fexp(m0 - mn0), al1 = fexp(m1 - mn1);

        float s0 = 0.f, s1 = 0.f;
#pragma unroll
        for (int f = 0; f < 8; f++) {
            S[f][0] = fexp(S[f][0] - mn0);
            S[f][1] = fexp(S[f][1] - mn0);
            S[f][2] = fexp(S[f][2] - mn1);
            S[f][3] = fexp(S[f][3] - mn1);
            s0 += S[f][0] + S[f][1];
            s1 += S[f][2] + S[f][3];
        }
        s0 += __shfl_xor_sync(0xffffffffu, s0, 1);
        s0 += __shfl_xor_sync(0xffffffffu, s0, 2);
        s1 += __shfl_xor_sync(0xffffffffu, s1, 1);
        s1 += __shfl_xor_sync(0xffffffffu, s1, 2);
        l0 = l0 * al0 + s0;
        l1 = l1 * al1 + s1;
        m0 = mn0; m1 = mn1;

#pragma unroll
        for (int d = 0; d < 16; d++) {
            o[d][0] *= al0; o[d][1] *= al0;
            o[d][2] *= al1; o[d][3] *= al1;
        }

        uint32_t pa[4][4];
#pragma unroll
        for (int kk = 0; kk < 4; kk++) {
            pa[kk][0] = packh2(S[2*kk][0],   S[2*kk][1]);
            pa[kk][1] = packh2(S[2*kk][2],   S[2*kk][3]);
            pa[kk][2] = packh2(S[2*kk+1][0], S[2*kk+1][1]);
            pa[kk][3] = packh2(S[2*kk+1][2], S[2*kk+1][3]);
        }

#pragma unroll
        for (int kk = 0; kk < 4; kk++) {
#pragma unroll
            for (int dg = 0; dg < 8; dg++) {
                uint32_t bv[4];
                ldm4t(bv, vbs + ((kk * 16 + aVrow) * AS + dg * 16 + aVcb) * 2);
                mmah(o[dg*2],   pa[kk], &bv[0]);
                mmah(o[dg*2+1], pa[kk], &bv[2]);
            }
        }
    }

    const float inv0 = 1.f / l0, inv1 = 1.f / l1;
    const int gr0 = b * QL + qt * 128 + w * 16 + r0;
    const int gr1 = gr0 + 8;
    const int col = h * HDD + (lane & 3) * 2;
#pragma unroll
    for (int d = 0; d < 16; d++) {
        *(__half2*)(obuf + (size_t)gr0 * HID + col + d * 8) = __floats2half2_rn(o[d][0] * inv0, o[d][1] * inv0);
        *(__half2*)(obuf + (size_t)gr1 * HID + col + d * 8) = __floats2half2_rn(o[d][2] * inv1, o[d][3] * inv1);
    }
}

// ============================================================
// launch — fork/join streams so independent prep kernels overlap
// ============================================================
extern "C" void kernel_launch(void* const* d_in, const int* in_sizes, int n_in,
                              void* d_out, int out_size)
{
    const float* hidden = (const float*)d_in[0];
    const float* Wq     = (const float*)d_in[1];
    const float* Wk     = (const float*)d_in[2];
    const float* Wv     = (const float*)d_in[3];
    const float* Wo     = (const float*)d_in[4];
    const float* kcache = (const float*)d_in[5];
    const float* vcache = (const float*)d_in[6];
    const int*   boff   = (const int*)d_in[7];
    const int*   pos    = (const int*)d_in[8];
    float* out = (float*)d_out;

    float2* cs;
    __half *ah, *wt, *qh, *khi, *klo, *vh;
    cudaGetSymbolAddress((void**)&cs, g_cs);
    cudaGetSymbolAddress((void**)&ah, g_Ah);
    cudaGetSymbolAddress((void**)&wt, g_Wt);
    cudaGetSymbolAddress((void**)&qh, g_Qh);
    cudaGetSymbolAddress((void**)&khi, g_Khi);
    cudaGetSymbolAddress((void**)&klo, g_Klo);
    cudaGetSymbolAddress((void**)&vh, g_Vh);

    // one-time setup (runs during the uncaptured correctness call first)
    static bool s_init = false;
    static cudaStream_t s_str[3];
    static cudaEvent_t  s_root, s_ev[3];
    if (!s_init) {
        cudaFuncSetAttribute(gemm_qkv, cudaFuncAttributeMaxDynamicSharedMemorySize, GEMM_SMEM);
        cudaFuncSetAttribute(gemm_single, cudaFuncAttributeMaxDynamicSharedMemorySize, GEMM_SMEM);
        cudaFuncSetAttribute(attn_mma, cudaFuncAttributeMaxDynamicSharedMemorySize, ATT_SMEM);
        for (int i = 0; i < 3; i++)
            cudaStreamCreateWithFlags(&s_str[i], cudaStreamNonBlocking);
        cudaEventCreateWithFlags(&s_root, cudaEventDisableTiming);
        for (int i = 0; i < 3; i++)
            cudaEventCreateWithFlags(&s_ev[i], cudaEventDisableTiming);
        s_init = true;
    }

    const int ncvt = TOK * HID / 4 / 256;
    dim3 tgrid(HID / 32, HID / 32, 4);

    // fork
    cudaEventRecord(s_root, 0);
    cudaStreamWaitEvent(s_str[0], s_root, 0);
    cudaStreamWaitEvent(s_str[1], s_root, 0);
    cudaStreamWaitEvent(s_str[2], s_root, 0);

    // side streams: independent prep
    rope_tab<<<TOK * 64 / 256, 256, 0, s_str[0]>>>(pos, cs);
    cudaEventRecord(s_ev[0], s_str[0]);

    transpose_half4<<<tgrid, 256, 0, s_str[1]>>>(Wq, Wk, Wv, Wo, wt);
    cudaEventRecord(s_ev[1], s_str[1]);

    hist_prep<<<NB * NHD * HIS / 8, 256, 0, s_str[2]>>>(kcache, vcache, boff, khi, klo, vh);
    cudaEventRecord(s_ev[2], s_str[2]);

    // main stream: A convert (runs concurrently with side streams)
    cvt_half<<<ncvt, 256>>>((const float4*)hidden, ah);

    // join rope_tab + transpose before QKV GEMM
    cudaStreamWaitEvent(0, s_ev[0], 0);
    cudaStreamWaitEvent(0, s_ev[1], 0);

    dim3 qkvgrid(3 * HID / 128, TOK / 128);
    gemm_qkv<<<qkvgrid, 128, GEMM_SMEM>>>(ah, wt, cs, qh, khi, klo, vh);

    // join hist_prep before attention (hidden under the QKV GEMM)
    cudaStreamWaitEvent(0, s_ev[2], 0);

    dim3 ag(NHD, NB, QL / 128);
    attn_mma<<<ag, 256, ATT_SMEM>>>(qh, khi, klo, vh, ah);

    dim3 ogrid(HID / 128, TOK / 128);
    gemm_single<<<ogrid, 128, GEMM_SMEM>>>(ah, wt + 3 * (size_t)HID * HID, out);
}